// round 3
// baseline (speedup 1.0000x reference)
#include <cuda_runtime.h>
#include <stdint.h>
#include <math.h>

// Sizes (fixed for this problem)
#define BB 16
#define LL 128
#define HH 256
#define DD 256
#define BL (BB*LL)              // 2048
#define NEL (BB*LL*LL)          // 262144
#define OFF_MS 0
#define OFF_S  NEL              // 262144
#define OFF_E  (2*NEL)          // 524288
#define OFF_GB (3*NEL)          // 786432
#define OFF_LSM (3*NEL + LL*LL) // 802816
#define OFF_ER (OFF_LSM + 1)    // 802817

// Scratch (no cudaMalloc allowed)
__device__ float g_dotl[BL*DD];
__device__ float g_dotr[BL*DD];
__device__ float g_lsm_part[BB];

// ---------------------------------------------------------------------------
// GEMM: C = A(2048x256) @ W(256x256), fp32 accumulate (NOT tf32)
// grid (4, 32, 2): x = n-tile(64), y = m-tile(64), z selects (W_l -> g_dotl) / (W_r -> g_dotr)
// block 256 threads, 4x4 microtile
// ---------------------------------------------------------------------------
__global__ void gemm_kernel(const float* __restrict__ A,
                            const float* __restrict__ Wl,
                            const float* __restrict__ Wr) {
    const float* W = blockIdx.z ? Wr : Wl;
    float* C = blockIdx.z ? g_dotr : g_dotl;
    __shared__ float As[16][65];   // [k][m], padded
    __shared__ float Bs[16][64];   // [k][n]
    const int tid = threadIdx.x;
    const int tx = tid & 15, ty = tid >> 4;
    const int m0 = blockIdx.y * 64, n0 = blockIdx.x * 64;

    float acc[4][4];
#pragma unroll
    for (int u = 0; u < 4; u++)
#pragma unroll
        for (int v = 0; v < 4; v++) acc[u][v] = 0.0f;

    for (int k0 = 0; k0 < 256; k0 += 16) {
        // load A tile 64x16 (float4, coalesced) -> As[k][m]
        {
            int ar = tid >> 2, ac = (tid & 3) << 2;
            float4 va = *(const float4*)(A + (m0 + ar) * 256 + k0 + ac);
            As[ac + 0][ar] = va.x; As[ac + 1][ar] = va.y;
            As[ac + 2][ar] = va.z; As[ac + 3][ar] = va.w;
        }
        // load B tile 16x64 (float4, coalesced) -> Bs[k][n]
        {
            int br = tid >> 4, bc = (tid & 15) << 2;
            float4 vb = *(const float4*)(W + (k0 + br) * 256 + n0 + bc);
            *(float4*)&Bs[br][bc] = vb;
        }
        __syncthreads();
#pragma unroll
        for (int kk = 0; kk < 16; kk++) {
            float a[4], b[4];
#pragma unroll
            for (int u = 0; u < 4; u++) a[u] = As[kk][ty + 16 * u];
#pragma unroll
            for (int v = 0; v < 4; v++) b[v] = Bs[kk][tx + 16 * v];
#pragma unroll
            for (int u = 0; u < 4; u++)
#pragma unroll
                for (int v = 0; v < 4; v++)
                    acc[u][v] = fmaf(a[u], b[v], acc[u][v]);
        }
        __syncthreads();
    }
#pragma unroll
    for (int u = 0; u < 4; u++)
#pragma unroll
        for (int v = 0; v < 4; v++)
            C[(m0 + ty + 16 * u) * 256 + n0 + tx + 16 * v] = acc[u][v];
}

// ---------------------------------------------------------------------------
// Threefry-2x32, key = (0, 1)  [jax.random.key(1)], partitionable random bits:
// per flat index i: x = (hi=0, lo=i), 20 rounds, bits = out0 ^ out1
// ---------------------------------------------------------------------------
__device__ __forceinline__ uint32_t rotl32(uint32_t v, int r) {
    return __funnelshift_l(v, v, r);
}

__device__ __forceinline__ uint32_t threefry_bits(uint32_t idx) {
    const uint32_t K0 = 0u, K1 = 1u, K2 = 0x1BD11BDBu; // K0^K1^0x1BD11BDA
    uint32_t x0 = K0;          // counts_hi (=0) + ks0
    uint32_t x1 = idx + K1;    // counts_lo + ks1
#define TF_ROUND(r) { x0 += x1; x1 = rotl32(x1, (r)); x1 ^= x0; }
    TF_ROUND(13) TF_ROUND(15) TF_ROUND(26) TF_ROUND(6)
    x0 += K1; x1 += K2 + 1u;
    TF_ROUND(17) TF_ROUND(29) TF_ROUND(16) TF_ROUND(24)
    x0 += K2; x1 += K0 + 2u;
    TF_ROUND(13) TF_ROUND(15) TF_ROUND(26) TF_ROUND(6)
    x0 += K0; x1 += K1 + 3u;
    TF_ROUND(17) TF_ROUND(29) TF_ROUND(16) TF_ROUND(24)
    x0 += K1; x1 += K2 + 4u;
    TF_ROUND(13) TF_ROUND(15) TF_ROUND(26) TF_ROUND(6)
    x0 += K2; x1 += K0 + 5u;
#undef TF_ROUND
    return x0 ^ x1;
}

// Fast accurate-enough tanh: 1 - 2/(1 + e^{2x}); ex2.approx + rcp.approx
// abs err ~1e-6 over the whole range, correct saturation at +-1 / inf handling.
__device__ __forceinline__ float tanh_fast(float x) {
    float e;
    asm("ex2.approx.f32 %0, %1;" : "=f"(e) : "f"(x * 2.885390081777927f)); // 2*log2(e)
    float r;
    asm("rcp.approx.f32 %0, %1;" : "=f"(r) : "f"(e + 1.0f));
    return fmaf(-2.0f, r, 1.0f);
}

__device__ __forceinline__ void epilogue(int b, int i, int j, float logit,
                                         float* __restrict__ out) {
    float ms = (i == j) ? (logit - 1e8f) : logit;
    uint32_t f = ((uint32_t)b << 14) | ((uint32_t)i << 7) | (uint32_t)j;
    uint32_t bits = threefry_bits(f);
    float u = __uint_as_float((bits >> 9) | 0x3f800000u) - 1.0f; // uniform [0,1)
    float p = 1.0f / (1.0f + expf(-ms));         // sigmoid (accurate; 0 on diag)
    float s = (u < p) ? 1.0f : 0.0f;             // bernoulli sample
    float c = log1pf(expf(-fabsf(ms)));          // shared softplus tail
    float sp_pos = fmaxf(ms, 0.0f) + c;          // softplus(ms)
    float sp_neg = fmaxf(-ms, 0.0f) + c;         // softplus(-ms)
    float ent = fmaf(p, sp_neg, (1.0f - p) * sp_pos);
    out[OFF_MS + f] = ms;
    out[OFF_S + f]  = s;
    out[OFF_E + f]  = ent;
}

// ---------------------------------------------------------------------------
// Pairwise additive-attention core.
// grid (4, 4, 16): x = j-tile(32), y = i-tile(32), z = batch; 256 threads.
// Each thread: 2x2 microtile (i, i+16) x (j, j+16). smem stride 129 ->
// conflict-free r-reads, broadcast l-reads. d processed in 2 chunks of 128.
// ---------------------------------------------------------------------------
__global__ void pairwise_kernel(const float* __restrict__ Uv,
                                const float* __restrict__ biasp,
                                float* __restrict__ out) {
    __shared__ float sl[32 * 129];
    __shared__ float sr[32 * 129];
    __shared__ float su[256];
    const int tid = threadIdx.x;
    const int tx = tid & 15, ty = tid >> 4;
    const int b = blockIdx.z;
    const int ibase = blockIdx.y * 32, jbase = blockIdx.x * 32;

    su[tid] = Uv[tid];

    float a00 = 0.f, a01 = 0.f, a10 = 0.f, a11 = 0.f;

    for (int k0 = 0; k0 < 256; k0 += 128) {
        __syncthreads();
        for (int idx = tid; idx < 32 * 128; idx += 256) {
            int r = idx >> 7, c = idx & 127;
            sl[r * 129 + c] = g_dotl[(b * 128 + ibase + r) * 256 + k0 + c];
            sr[r * 129 + c] = g_dotr[(b * 128 + jbase + r) * 256 + k0 + c];
        }
        __syncthreads();
        const float* pl0 = sl + ty * 129;
        const float* pl1 = sl + (ty + 16) * 129;
        const float* pr0 = sr + tx * 129;
        const float* pr1 = sr + (tx + 16) * 129;
        const float* pu  = su + k0;
#pragma unroll 4
        for (int d = 0; d < 128; d++) {
            float la = pl0[d], lb = pl1[d];
            float ra = pr0[d], rb = pr1[d];
            float ud = pu[d];
            a00 = fmaf(ud, tanh_fast(la + ra), a00);
            a01 = fmaf(ud, tanh_fast(la + rb), a01);
            a10 = fmaf(ud, tanh_fast(lb + ra), a10);
            a11 = fmaf(ud, tanh_fast(lb + rb), a11);
        }
    }

    const float bias = __ldg(biasp);
    epilogue(b, ibase + ty,      jbase + tx,      a00 + bias, out);
    epilogue(b, ibase + ty,      jbase + tx + 16, a01 + bias, out);
    epilogue(b, ibase + ty + 16, jbase + tx,      a10 + bias, out);
    epilogue(b, ibase + ty + 16, jbase + tx + 16, a11 + bias, out);
}

// ---------------------------------------------------------------------------
// graph_batch[i,j] = mean over b of samples  (exact: multiples of 1/16)
// ---------------------------------------------------------------------------
__global__ void gb_kernel(float* __restrict__ out) {
    int idx = blockIdx.x * 256 + threadIdx.x; // 0..16383
    float s = 0.0f;
#pragma unroll
    for (int b = 0; b < BB; b++)
        s += out[OFF_S + b * (LL * LL) + idx];
    out[OFF_GB + idx] = s * 0.0625f;
}

// ---------------------------------------------------------------------------
// Per-batch reductions: entropy_reg[b] and partial log_softmax sums.
// grid 16 (one block per b), 256 threads, deterministic tree reduce.
// ---------------------------------------------------------------------------
__global__ void red_kernel(float* __restrict__ out) {
    const int b = blockIdx.x, t = threadIdx.x;
    const float* ms = out + OFF_MS + b * (LL * LL);
    const float* sm = out + OFF_S  + b * (LL * LL);
    const float* en = out + OFF_E  + b * (LL * LL);
    float se = 0.0f, slsm = 0.0f;
    for (int k = t; k < LL * LL; k += 256) {
        se += en[k];
        float m = ms[k];
        float s = sm[k];
        float sp = fmaxf(m, 0.0f) + log1pf(expf(-fabsf(m))); // softplus(m)
        slsm += sp - m * s;
    }
    __shared__ float r1[256], r2[256];
    r1[t] = se; r2[t] = slsm;
    __syncthreads();
    for (int o = 128; o > 0; o >>= 1) {
        if (t < o) { r1[t] += r1[t + o]; r2[t] += r2[t + o]; }
        __syncthreads();
    }
    if (t == 0) {
        out[OFF_ER + b] = r1[0] * (1.0f / 16384.0f);
        g_lsm_part[b] = r2[0];
    }
}

__global__ void fin_kernel(float* __restrict__ out) {
    if (threadIdx.x == 0) {
        float tot = 0.0f;
#pragma unroll
        for (int b = 0; b < BB; b++) tot += g_lsm_part[b];
        out[OFF_LSM] = tot * (1.0f / (float)NEL);
    }
}

// ---------------------------------------------------------------------------
extern "C" void kernel_launch(void* const* d_in, const int* in_sizes, int n_in,
                              void* d_out, int out_size) {
    (void)in_sizes; (void)n_in; (void)out_size;
    const float* enc  = (const float*)d_in[0]; // (16,128,256)
    const float* W_l  = (const float*)d_in[1]; // (256,256)
    const float* W_r  = (const float*)d_in[2]; // (256,256)
    const float* U    = (const float*)d_in[3]; // (256,)
    const float* bias = (const float*)d_in[4]; // (1,)
    float* out = (float*)d_out;

    gemm_kernel<<<dim3(4, 32, 2), 256>>>(enc, W_l, W_r);
    pairwise_kernel<<<dim3(4, 4, 16), 256>>>(U, bias, out);
    gb_kernel<<<64, 256>>>(out);
    red_kernel<<<16, 256>>>(out);
    fin_kernel<<<1, 32>>>(out);
}

// round 4
// speedup vs baseline: 2.1739x; 2.1739x over previous
#include <cuda_runtime.h>
#include <stdint.h>
#include <math.h>

// Sizes (fixed for this problem)
#define BB 16
#define LL 128
#define HH 256
#define DD 256
#define BL (BB*LL)              // 2048
#define NEL (BB*LL*LL)          // 262144
#define OFF_MS 0
#define OFF_S  NEL              // 262144
#define OFF_E  (2*NEL)          // 524288
#define OFF_GB (3*NEL)          // 786432
#define OFF_LSM (3*NEL + LL*LL) // 802816
#define OFF_ER (OFF_LSM + 1)    // 802817

// Scratch (no cudaMalloc allowed). g_el/g_er hold exp(2*dot) = 2^(2.885*dot).
__device__ float g_el[BL*DD];
__device__ float g_er[BL*DD];
__device__ float g_ent_part[256];
__device__ float g_lsm_part[256];
__device__ int   g_cnt[LL*LL];   // zero-init at load; tail kernel resets each call

#define TWO_LOG2E 2.8853900817779268f   // 2*log2(e)

__device__ __forceinline__ float ex2f(float x) {
    float e; asm("ex2.approx.f32 %0, %1;" : "=f"(e) : "f"(x)); return e;
}
__device__ __forceinline__ float rcpf(float x) {
    float r; asm("rcp.approx.f32 %0, %1;" : "=f"(r) : "f"(x)); return r;
}

// ---------------------------------------------------------------------------
// GEMM: C = exp(2 * (A(2048x256) @ W(256x256))), fp32 accumulate.
// grid (4, 32, 2): x = n-tile(64), y = m-tile(64), z selects W_l/W_r
// ---------------------------------------------------------------------------
__global__ void gemm_exp_kernel(const float* __restrict__ A,
                                const float* __restrict__ Wl,
                                const float* __restrict__ Wr) {
    const float* W = blockIdx.z ? Wr : Wl;
    float* C = blockIdx.z ? g_er : g_el;
    __shared__ float As[16][65];   // [k][m], padded
    __shared__ float Bs[16][64];   // [k][n]
    const int tid = threadIdx.x;
    const int tx = tid & 15, ty = tid >> 4;
    const int m0 = blockIdx.y * 64, n0 = blockIdx.x * 64;

    float acc[4][4];
#pragma unroll
    for (int u = 0; u < 4; u++)
#pragma unroll
        for (int v = 0; v < 4; v++) acc[u][v] = 0.0f;

    for (int k0 = 0; k0 < 256; k0 += 16) {
        {
            int ar = tid >> 2, ac = (tid & 3) << 2;
            float4 va = *(const float4*)(A + (m0 + ar) * 256 + k0 + ac);
            As[ac + 0][ar] = va.x; As[ac + 1][ar] = va.y;
            As[ac + 2][ar] = va.z; As[ac + 3][ar] = va.w;
        }
        {
            int br = tid >> 4, bc = (tid & 15) << 2;
            float4 vb = *(const float4*)(W + (k0 + br) * 256 + n0 + bc);
            *(float4*)&Bs[br][bc] = vb;
        }
        __syncthreads();
#pragma unroll
        for (int kk = 0; kk < 16; kk++) {
            float a[4], b[4];
#pragma unroll
            for (int u = 0; u < 4; u++) a[u] = As[kk][ty + 16 * u];
#pragma unroll
            for (int v = 0; v < 4; v++) b[v] = Bs[kk][tx + 16 * v];
#pragma unroll
            for (int u = 0; u < 4; u++)
#pragma unroll
                for (int v = 0; v < 4; v++)
                    acc[u][v] = fmaf(a[u], b[v], acc[u][v]);
        }
        __syncthreads();
    }
#pragma unroll
    for (int u = 0; u < 4; u++)
#pragma unroll
        for (int v = 0; v < 4; v++)
            C[(m0 + ty + 16 * u) * 256 + n0 + tx + 16 * v] =
                ex2f(acc[u][v] * TWO_LOG2E);
}

// ---------------------------------------------------------------------------
// Threefry-2x32, key = (0,1) [jax.random.key(1)], partitionable bits.
// ---------------------------------------------------------------------------
__device__ __forceinline__ uint32_t rotl32(uint32_t v, int r) {
    return __funnelshift_l(v, v, r);
}
__device__ __forceinline__ uint32_t threefry_bits(uint32_t idx) {
    const uint32_t K0 = 0u, K1 = 1u, K2 = 0x1BD11BDBu;
    uint32_t x0 = K0;
    uint32_t x1 = idx + K1;
#define TF_ROUND(r) { x0 += x1; x1 = rotl32(x1, (r)); x1 ^= x0; }
    TF_ROUND(13) TF_ROUND(15) TF_ROUND(26) TF_ROUND(6)
    x0 += K1; x1 += K2 + 1u;
    TF_ROUND(17) TF_ROUND(29) TF_ROUND(16) TF_ROUND(24)
    x0 += K2; x1 += K0 + 2u;
    TF_ROUND(13) TF_ROUND(15) TF_ROUND(26) TF_ROUND(6)
    x0 += K0; x1 += K1 + 3u;
    TF_ROUND(17) TF_ROUND(29) TF_ROUND(16) TF_ROUND(24)
    x0 += K1; x1 += K2 + 4u;
    TF_ROUND(13) TF_ROUND(15) TF_ROUND(26) TF_ROUND(6)
    x0 += K2; x1 += K0 + 5u;
#undef TF_ROUND
    return x0 ^ x1;
}

// Epilogue for one (b,i,j): writes ms/sample/entropy, counts sample into
// g_cnt (integer atomic -> deterministic), returns (entropy, lsm_term).
__device__ __forceinline__ float2 epi_one(int b, int i, int j, float logit,
                                          float* __restrict__ out) {
    float ms = (i == j) ? (logit - 1e8f) : logit;
    uint32_t f = ((uint32_t)b << 14) | ((uint32_t)i << 7) | (uint32_t)j;
    uint32_t bits = threefry_bits(f);
    float u = __uint_as_float((bits >> 9) | 0x3f800000u) - 1.0f;
    float p = 1.0f / (1.0f + expf(-ms));
    float c = log1pf(expf(-fabsf(ms)));          // shared softplus tail
    float sp_pos = fmaxf(ms, 0.0f) + c;          // softplus(ms)
    float sp_neg = fmaxf(-ms, 0.0f) + c;         // softplus(-ms)
    float ent = fmaf(p, sp_neg, (1.0f - p) * sp_pos);
    float s;
    if (u < p) { s = 1.0f; atomicAdd(&g_cnt[i * LL + j], 1); } else s = 0.0f;
    out[OFF_MS + f] = ms;
    out[OFF_S + f]  = s;
    out[OFF_E + f]  = ent;
    float lsm = sp_pos - ms * s;
    return make_float2(ent, lsm);
}

// ---------------------------------------------------------------------------
// Pairwise core. tanh(l+r) = 1 - 2/(1 + el*er); logit = -2*sum U*(r-0.5).
// grid (4,4,16): x=j-tile(32), y=i-tile(32), z=batch; 256 threads (16x16),
// 2x2 microtile. smem stride 132 -> float4, conflict-free. d in 2 chunks.
// ---------------------------------------------------------------------------
__global__ void pairwise_kernel(const float* __restrict__ Uv,
                                const float* __restrict__ biasp,
                                float* __restrict__ out) {
    __shared__ __align__(16) float sl[32 * 132];
    __shared__ __align__(16) float sr[32 * 132];
    __shared__ __align__(16) float su[256];
    __shared__ float red[256];
    const int tid = threadIdx.x;
    const int tx = tid & 15, ty = tid >> 4;
    const int b = blockIdx.z;
    const int ibase = blockIdx.y * 32, jbase = blockIdx.x * 32;

    su[tid] = Uv[tid];

    float a00 = 0.f, a01 = 0.f, a10 = 0.f, a11 = 0.f;

    for (int k0 = 0; k0 < 256; k0 += 128) {
        __syncthreads();
        // 32 rows x 32 float4 per tile; 32 consecutive threads per row
        for (int idx = tid; idx < 32 * 32; idx += 256) {
            int r = idx >> 5, c = (idx & 31) << 2;
            *(float4*)&sl[r * 132 + c] =
                *(const float4*)&g_el[(b * 128 + ibase + r) * 256 + k0 + c];
            *(float4*)&sr[r * 132 + c] =
                *(const float4*)&g_er[(b * 128 + jbase + r) * 256 + k0 + c];
        }
        __syncthreads();
        const float* pl0 = sl + ty * 132;
        const float* pl1 = sl + (ty + 16) * 132;
        const float* pr0 = sr + tx * 132;
        const float* pr1 = sr + (tx + 16) * 132;
        const float* pu  = su + k0;
#pragma unroll 4
        for (int d = 0; d < 128; d += 4) {
            float4 LA = *(const float4*)(pl0 + d);
            float4 LB = *(const float4*)(pl1 + d);
            float4 RA = *(const float4*)(pr0 + d);
            float4 RB = *(const float4*)(pr1 + d);
            float4 UD = *(const float4*)(pu + d);
#define BODY(la, lb, ra, rb, ud)                                    \
            {                                                        \
                float r00 = rcpf(fmaf((la), (ra), 1.0f)) - 0.5f;     \
                float r01 = rcpf(fmaf((la), (rb), 1.0f)) - 0.5f;     \
                float r10 = rcpf(fmaf((lb), (ra), 1.0f)) - 0.5f;     \
                float r11 = rcpf(fmaf((lb), (rb), 1.0f)) - 0.5f;     \
                a00 = fmaf((ud), r00, a00);                          \
                a01 = fmaf((ud), r01, a01);                          \
                a10 = fmaf((ud), r10, a10);                          \
                a11 = fmaf((ud), r11, a11);                          \
            }
            BODY(LA.x, LB.x, RA.x, RB.x, UD.x)
            BODY(LA.y, LB.y, RA.y, RB.y, UD.y)
            BODY(LA.z, LB.z, RA.z, RB.z, UD.z)
            BODY(LA.w, LB.w, RA.w, RB.w, UD.w)
#undef BODY
        }
    }

    const float bias = __ldg(biasp);
    float2 e0 = epi_one(b, ibase + ty,      jbase + tx,      fmaf(-2.f, a00, bias), out);
    float2 e1 = epi_one(b, ibase + ty,      jbase + tx + 16, fmaf(-2.f, a01, bias), out);
    float2 e2 = epi_one(b, ibase + ty + 16, jbase + tx,      fmaf(-2.f, a10, bias), out);
    float2 e3 = epi_one(b, ibase + ty + 16, jbase + tx + 16, fmaf(-2.f, a11, bias), out);

    const int bid = (b * 4 + blockIdx.y) * 4 + blockIdx.x; // = b*16 + y*4 + x
    // block reduce entropy
    red[tid] = (e0.x + e1.x) + (e2.x + e3.x);
    __syncthreads();
    for (int o = 128; o > 0; o >>= 1) {
        if (tid < o) red[tid] += red[tid + o];
        __syncthreads();
    }
    if (tid == 0) g_ent_part[bid] = red[0];
    __syncthreads();
    // block reduce lsm
    red[tid] = (e0.y + e1.y) + (e2.y + e3.y);
    __syncthreads();
    for (int o = 128; o > 0; o >>= 1) {
        if (tid < o) red[tid] += red[tid + o];
        __syncthreads();
    }
    if (tid == 0) g_lsm_part[bid] = red[0];
}

// ---------------------------------------------------------------------------
// Tail: blocks 0-63 convert+reset graph_batch counts; block 64 finishes
// entropy_regularization (per-batch, fixed order) and log_softmax scalar.
// ---------------------------------------------------------------------------
__global__ void tail_kernel(float* __restrict__ out) {
    const int bidx = blockIdx.x;
    if (bidx < 64) {
        int idx = bidx * 256 + threadIdx.x;   // 0..16383
        out[OFF_GB + idx] = (float)g_cnt[idx] * 0.0625f;
        g_cnt[idx] = 0;                        // reset for next graph replay
    } else {
        int t = threadIdx.x;
        if (t < 16) {
            float s = 0.0f;
#pragma unroll
            for (int k = 0; k < 16; k++) s += g_ent_part[t * 16 + k];
            out[OFF_ER + t] = s * (1.0f / 16384.0f);
        }
        if (t == 16) {
            float s = 0.0f;
            for (int k = 0; k < 256; k++) s += g_lsm_part[k];
            out[OFF_LSM] = s * (1.0f / (float)NEL);
        }
    }
}

// ---------------------------------------------------------------------------
extern "C" void kernel_launch(void* const* d_in, const int* in_sizes, int n_in,
                              void* d_out, int out_size) {
    (void)in_sizes; (void)n_in; (void)out_size;
    const float* enc  = (const float*)d_in[0]; // (16,128,256)
    const float* W_l  = (const float*)d_in[1]; // (256,256)
    const float* W_r  = (const float*)d_in[2]; // (256,256)
    const float* U    = (const float*)d_in[3]; // (256,)
    const float* bias = (const float*)d_in[4]; // (1,)
    float* out = (float*)d_out;

    gemm_exp_kernel<<<dim3(4, 32, 2), 256>>>(enc, W_l, W_r);
    pairwise_kernel<<<dim3(4, 4, 16), 256>>>(U, bias, out);
    tail_kernel<<<65, 256>>>(out);
}

// round 6
// speedup vs baseline: 2.4699x; 1.1362x over previous
#include <cuda_runtime.h>
#include <stdint.h>
#include <math.h>

// Sizes (fixed for this problem)
#define BB 16
#define LL 128
#define HH 256
#define DD 256
#define BL (BB*LL)              // 2048
#define NEL (BB*LL*LL)          // 262144
#define OFF_MS 0
#define OFF_S  NEL              // 262144
#define OFF_E  (2*NEL)          // 524288
#define OFF_GB (3*NEL)          // 786432
#define OFF_LSM (3*NEL + LL*LL) // 802816
#define OFF_ER (OFF_LSM + 1)    // 802817

// Scratch (no cudaMalloc allowed). g_el/g_er hold exp(2*dot).
__device__ float g_el[BL*DD];
__device__ float g_er[BL*DD];
__device__ float g_ent_part[1024];
__device__ float g_lsm_part[1024];
__device__ int   g_cnt[LL*LL];   // zero at load; tail kernel resets each call

#define TWO_LOG2E 2.8853900817779268f   // 2*log2(e)

__device__ __forceinline__ float ex2f(float x) {
    float e; asm("ex2.approx.f32 %0, %1;" : "=f"(e) : "f"(x)); return e;
}
__device__ __forceinline__ float rcpf(float x) {
    float r; asm("rcp.approx.f32 %0, %1;" : "=f"(r) : "f"(x)); return r;
}

// ---------------------------------------------------------------------------
// GEMM: C = exp(2 * (A(2048x256) @ W(256x256))), fp32.
// 64x64 tile, k-chunk 32 per stage, register prefetch.
// As[m][k] stride 36 (LDS.128 a-frags, broadcast), Bs[k][n] stride 68
// (scalar b-reads, conflict-free). grid (4, 32, 2), 256 threads.
// ---------------------------------------------------------------------------
__global__ __launch_bounds__(256, 2)
void gemm_exp_kernel(const float* __restrict__ A,
                     const float* __restrict__ Wl,
                     const float* __restrict__ Wr) {
    const float* W = blockIdx.z ? Wr : Wl;
    float* C = blockIdx.z ? g_er : g_el;
    __shared__ float As[64 * 36];
    __shared__ float Bs[32 * 68];
    const int tid = threadIdx.x;
    const int tx = tid & 15, ty = tid >> 4;
    const int m0 = blockIdx.y * 64, n0 = blockIdx.x * 64;

    const int ar = tid >> 2, ac = (tid & 3) * 8;  // A tile: 64 rows x 32 cols
    const int br = tid >> 3, bc = (tid & 7) * 8;  // W tile: 32 rows x 64 cols
    const float* Ap = A + (m0 + ar) * 256 + ac;
    const float* Wp = W + br * 256 + n0 + bc;

    float4 ra0 = *(const float4*)(Ap + 0);
    float4 ra1 = *(const float4*)(Ap + 4);
    float4 rb0 = *(const float4*)(Wp + 0);
    float4 rb1 = *(const float4*)(Wp + 4);

    float acc[4][4];
#pragma unroll
    for (int u = 0; u < 4; u++)
#pragma unroll
        for (int v = 0; v < 4; v++) acc[u][v] = 0.0f;

    for (int s = 0; s < 8; s++) {
        *(float4*)&As[ar * 36 + ac]     = ra0;
        *(float4*)&As[ar * 36 + ac + 4] = ra1;
        *(float4*)&Bs[br * 68 + bc]     = rb0;
        *(float4*)&Bs[br * 68 + bc + 4] = rb1;
        __syncthreads();
        if (s < 7) {
            ra0 = *(const float4*)(Ap + (s + 1) * 32 + 0);
            ra1 = *(const float4*)(Ap + (s + 1) * 32 + 4);
            rb0 = *(const float4*)(Wp + (s + 1) * 32 * 256 + 0);
            rb1 = *(const float4*)(Wp + (s + 1) * 32 * 256 + 4);
        }
#pragma unroll
        for (int kq = 0; kq < 32; kq += 4) {
            float4 a0 = *(const float4*)&As[(ty     ) * 36 + kq];
            float4 a1 = *(const float4*)&As[(ty + 16) * 36 + kq];
            float4 a2 = *(const float4*)&As[(ty + 32) * 36 + kq];
            float4 a3 = *(const float4*)&As[(ty + 48) * 36 + kq];
#define KSTEP(KK, CMP)                                                        \
            {                                                                 \
                const float* bp = &Bs[(kq + KK) * 68 + tx];                   \
                float b0 = bp[0], b1 = bp[16], b2 = bp[32], b3 = bp[48];      \
                acc[0][0] = fmaf(a0.CMP, b0, acc[0][0]);                      \
                acc[0][1] = fmaf(a0.CMP, b1, acc[0][1]);                      \
                acc[0][2] = fmaf(a0.CMP, b2, acc[0][2]);                      \
                acc[0][3] = fmaf(a0.CMP, b3, acc[0][3]);                      \
                acc[1][0] = fmaf(a1.CMP, b0, acc[1][0]);                      \
                acc[1][1] = fmaf(a1.CMP, b1, acc[1][1]);                      \
                acc[1][2] = fmaf(a1.CMP, b2, acc[1][2]);                      \
                acc[1][3] = fmaf(a1.CMP, b3, acc[1][3]);                      \
                acc[2][0] = fmaf(a2.CMP, b0, acc[2][0]);                      \
                acc[2][1] = fmaf(a2.CMP, b1, acc[2][1]);                      \
                acc[2][2] = fmaf(a2.CMP, b2, acc[2][2]);                      \
                acc[2][3] = fmaf(a2.CMP, b3, acc[2][3]);                      \
                acc[3][0] = fmaf(a3.CMP, b0, acc[3][0]);                      \
                acc[3][1] = fmaf(a3.CMP, b1, acc[3][1]);                      \
                acc[3][2] = fmaf(a3.CMP, b2, acc[3][2]);                      \
                acc[3][3] = fmaf(a3.CMP, b3, acc[3][3]);                      \
            }
            KSTEP(0, x) KSTEP(1, y) KSTEP(2, z) KSTEP(3, w)
#undef KSTEP
        }
        __syncthreads();
    }
#pragma unroll
    for (int u = 0; u < 4; u++)
#pragma unroll
        for (int v = 0; v < 4; v++)
            C[(m0 + ty + 16 * u) * 256 + n0 + tx + 16 * v] =
                ex2f(acc[u][v] * TWO_LOG2E);
}

// ---------------------------------------------------------------------------
// Threefry-2x32, key = (0,1) [jax.random.key(1)], partitionable bits.
// ---------------------------------------------------------------------------
__device__ __forceinline__ uint32_t rotl32(uint32_t v, int r) {
    return __funnelshift_l(v, v, r);
}
__device__ __forceinline__ uint32_t threefry_bits(uint32_t idx) {
    const uint32_t K0 = 0u, K1 = 1u, K2 = 0x1BD11BDBu;
    uint32_t x0 = K0;
    uint32_t x1 = idx + K1;
#define TF_ROUND(r) { x0 += x1; x1 = rotl32(x1, (r)); x1 ^= x0; }
    TF_ROUND(13) TF_ROUND(15) TF_ROUND(26) TF_ROUND(6)
    x0 += K1; x1 += K2 + 1u;
    TF_ROUND(17) TF_ROUND(29) TF_ROUND(16) TF_ROUND(24)
    x0 += K2; x1 += K0 + 2u;
    TF_ROUND(13) TF_ROUND(15) TF_ROUND(26) TF_ROUND(6)
    x0 += K0; x1 += K1 + 3u;
    TF_ROUND(17) TF_ROUND(29) TF_ROUND(16) TF_ROUND(24)
    x0 += K1; x1 += K2 + 4u;
    TF_ROUND(13) TF_ROUND(15) TF_ROUND(26) TF_ROUND(6)
    x0 += K2; x1 += K0 + 5u;
#undef TF_ROUND
    return x0 ^ x1;
}

// Epilogue for one (b,i,j): writes ms/sample/entropy, counts sample into
// g_cnt (integer atomic -> deterministic), returns (entropy, lsm_term).
__device__ __forceinline__ float2 epi_one(int b, int i, int j, float logit,
                                          float* __restrict__ out) {
    float ms = (i == j) ? (logit - 1e8f) : logit;
    uint32_t f = ((uint32_t)b << 14) | ((uint32_t)i << 7) | (uint32_t)j;
    uint32_t bits = threefry_bits(f);
    float u = __uint_as_float((bits >> 9) | 0x3f800000u) - 1.0f;
    float p = 1.0f / (1.0f + expf(-ms));
    float c = log1pf(expf(-fabsf(ms)));          // shared softplus tail
    float sp_pos = fmaxf(ms, 0.0f) + c;          // softplus(ms)
    float sp_neg = fmaxf(-ms, 0.0f) + c;         // softplus(-ms)
    float ent = fmaf(p, sp_neg, (1.0f - p) * sp_pos);
    float s;
    if (u < p) { s = 1.0f; atomicAdd(&g_cnt[i * LL + j], 1); } else s = 0.0f;
    out[OFF_MS + f] = ms;
    out[OFF_S + f]  = s;
    out[OFF_E + f]  = ent;
    float lsm = sp_pos - ms * s;
    return make_float2(ent, lsm);
}

// ---------------------------------------------------------------------------
// Pairwise core. tanh(l+r) = 1 - 2/(1 + el*er); logit = -2*sum U*(r-0.5) + bias.
// grid (16, 4, 16): x = j-tile(8), y = i-tile(32), z = batch; 256 threads
// (ty = i 0..31, tx = j 0..7), 1 element/thread, full D=256 in smem.
// 1024 blocks stream over ~4-5 resident/SM -> no mod-148 wave quantization.
// ---------------------------------------------------------------------------
#define PW_STR 260

__global__ __launch_bounds__(256, 4)
void pairwise_kernel(const float* __restrict__ Uv,
                     const float* __restrict__ biasp,
                     float* __restrict__ out) {
    __shared__ __align__(16) float sl[32 * PW_STR];
    __shared__ __align__(16) float sr[8 * PW_STR];
    __shared__ __align__(16) float su[256];
    __shared__ float rshare[2][8];
    const int tid = threadIdx.x;
    const int tx = tid & 7, ty = tid >> 3;        // j, i within tile
    const int b = blockIdx.z;
    const int ibase = blockIdx.y * 32, jbase = blockIdx.x * 8;

    su[tid] = Uv[tid];
    // load 32 l-rows + 8 r-rows, each 256 floats (64 float4), coalesced
    for (int idx = tid; idx < 40 * 64; idx += 256) {
        int r = idx >> 6, c = (idx & 63) * 4;
        if (r < 32) {
            *(float4*)&sl[r * PW_STR + c] =
                *(const float4*)&g_el[(b * 128 + ibase + r) * 256 + c];
        } else {
            *(float4*)&sr[(r - 32) * PW_STR + c] =
                *(const float4*)&g_er[(b * 128 + jbase + (r - 32)) * 256 + c];
        }
    }
    __syncthreads();

    const float* pl = sl + ty * PW_STR;
    const float* pr = sr + tx * PW_STR;
    float a0 = 0.0f;
#pragma unroll 4
    for (int d = 0; d < 256; d += 4) {
        float4 L  = *(const float4*)(pl + d);
        float4 R  = *(const float4*)(pr + d);
        float4 UD = *(const float4*)(su + d);
        a0 = fmaf(UD.x, rcpf(fmaf(L.x, R.x, 1.0f)) - 0.5f, a0);
        a0 = fmaf(UD.y, rcpf(fmaf(L.y, R.y, 1.0f)) - 0.5f, a0);
        a0 = fmaf(UD.z, rcpf(fmaf(L.z, R.z, 1.0f)) - 0.5f, a0);
        a0 = fmaf(UD.w, rcpf(fmaf(L.w, R.w, 1.0f)) - 0.5f, a0);
    }

    const float bias = __ldg(biasp);
    float2 e = epi_one(b, ibase + ty, jbase + tx, fmaf(-2.0f, a0, bias), out);

    // block reduce (shfl tree + 8-warp combine), deterministic
    float ent = e.x, lsm = e.y;
#pragma unroll
    for (int o = 16; o > 0; o >>= 1) {
        ent += __shfl_xor_sync(0xffffffffu, ent, o);
        lsm += __shfl_xor_sync(0xffffffffu, lsm, o);
    }
    const int wid = tid >> 5;
    if ((tid & 31) == 0) { rshare[0][wid] = ent; rshare[1][wid] = lsm; }
    __syncthreads();
    if (tid == 0) {
        float se = 0.0f, sm = 0.0f;
#pragma unroll
        for (int w = 0; w < 8; w++) { se += rshare[0][w]; sm += rshare[1][w]; }
        const int bid = (b * 4 + blockIdx.y) * 16 + blockIdx.x; // 0..1023
        g_ent_part[bid] = se;
        g_lsm_part[bid] = sm;
    }
}

// ---------------------------------------------------------------------------
// Tail: blocks 0-63 convert+reset graph_batch counts; block 64 finishes
// entropy_regularization (16 per-batch sums of 64 partials, fixed order)
// and the log_softmax scalar (warp 1 reduces 1024 partials).
// ---------------------------------------------------------------------------
__global__ void tail_kernel(float* __restrict__ out) {
    const int bidx = blockIdx.x;
    if (bidx < 64) {
        int idx = bidx * 256 + threadIdx.x;   // 0..16383
        out[OFF_GB + idx] = (float)g_cnt[idx] * 0.0625f;
        g_cnt[idx] = 0;                        // reset for next graph replay
    } else {
        int t = threadIdx.x;
        if (t < 16) {
            float s = 0.0f;
#pragma unroll
            for (int k = 0; k < 64; k++) s += g_ent_part[t * 64 + k];
            out[OFF_ER + t] = s * (1.0f / 16384.0f);
        }
        if (t >= 32 && t < 64) {
            int lane = t - 32;
            float s = 0.0f;
#pragma unroll
            for (int k = 0; k < 32; k++) s += g_lsm_part[lane * 32 + k];
#pragma unroll
            for (int o = 16; o > 0; o >>= 1)
                s += __shfl_xor_sync(0xffffffffu, s, o);
            if (lane == 0) out[OFF_LSM] = s * (1.0f / (float)NEL);
        }
    }
}

// ---------------------------------------------------------------------------
extern "C" void kernel_launch(void* const* d_in, const int* in_sizes, int n_in,
                              void* d_out, int out_size) {
    (void)in_sizes; (void)n_in; (void)out_size;
    const float* enc  = (const float*)d_in[0]; // (16,128,256)
    const float* W_l  = (const float*)d_in[1]; // (256,256)
    const float* W_r  = (const float*)d_in[2]; // (256,256)
    const float* U    = (const float*)d_in[3]; // (256,)
    const float* bias = (const float*)d_in[4]; // (1,)
    float* out = (float*)d_out;

    gemm_exp_kernel<<<dim3(4, 32, 2), 256>>>(enc, W_l, W_r);
    pairwise_kernel<<<dim3(16, 4, 16), 256>>>(U, bias, out);
    tail_kernel<<<65, 256>>>(out);
}

// round 8
// speedup vs baseline: 2.5185x; 1.0197x over previous
#include <cuda_runtime.h>
#include <stdint.h>
#include <math.h>

// Sizes (fixed for this problem)
#define BB 16
#define LL 128
#define HH 256
#define DD 256
#define BL (BB*LL)              // 2048
#define NEL (BB*LL*LL)          // 262144
#define OFF_MS 0
#define OFF_S  NEL              // 262144
#define OFF_E  (2*NEL)          // 524288
#define OFF_GB (3*NEL)          // 786432
#define OFF_LSM (3*NEL + LL*LL) // 802816
#define OFF_ER (OFF_LSM + 1)    // 802817

// Scratch (no cudaMalloc allowed). g_el/g_er hold exp(2*dot).
__device__ float g_el[BL*DD];
__device__ float g_er[BL*DD];
__device__ float g_ent_part[512];
__device__ float g_lsm_part[512];
__device__ int   g_cnt[LL*LL];   // zero at load; tail kernel resets each call

#define TWO_LOG2E 2.8853900817779268f   // 2*log2(e)

__device__ __forceinline__ float ex2f(float x) {
    float e; asm("ex2.approx.f32 %0, %1;" : "=f"(e) : "f"(x)); return e;
}
__device__ __forceinline__ float rcpf(float x) {
    float r; asm("rcp.approx.f32 %0, %1;" : "=f"(r) : "f"(x)); return r;
}

// ---------------------------------------------------------------------------
// GEMM: C = exp(2 * (A(2048x256) @ W(256x256))), fp32.
// 64x64 tile, 128 threads, 8x4 microtile, k-chunk 16, register prefetch.
// As[m][k] stride 20 (LDS.128 a-frags along k), Bs[k][n] stride 68
// (LDS.128 b-frags along n). 12 LDS.128 per 128 FMA.
// grid (4, 32, 2) = 256 blocks -> single wave @ occ 2.
// ---------------------------------------------------------------------------
#define AS_STR 20
#define BS_STR 68

__global__ __launch_bounds__(128, 2)
void gemm_exp_kernel(const float* __restrict__ A,
                     const float* __restrict__ Wl,
                     const float* __restrict__ Wr) {
    const float* W = blockIdx.z ? Wr : Wl;
    float* C = blockIdx.z ? g_er : g_el;
    __shared__ __align__(16) float As[64 * AS_STR];
    __shared__ __align__(16) float Bs[16 * BS_STR];
    const int tid = threadIdx.x;
    const int tx = tid & 15, ty = tid >> 4;       // tx: n (0..15), ty: m (0..7)
    const int m0 = blockIdx.y * 64, n0 = blockIdx.x * 64;

    // global load mapping
    const int arow = tid >> 2, acol = (tid & 3) * 4;   // A: 64 rows x 16 k
    const int brow = tid >> 3, bcol = (tid & 7) * 8;   // W: 16 rows x 64 n
    const float* Ap = A + (m0 + arow) * 256 + acol;
    const float* Wp = W + brow * 256 + n0 + bcol;

    float4 ra0 = *(const float4*)(Ap);
    float4 ra1 = *(const float4*)(Ap + 32 * 256);
    float4 rb0 = *(const float4*)(Wp);
    float4 rb1 = *(const float4*)(Wp + 4);

    float acc[8][4];
#pragma unroll
    for (int u = 0; u < 8; u++)
#pragma unroll
        for (int v = 0; v < 4; v++) acc[u][v] = 0.0f;

    for (int s = 0; s < 16; s++) {
        *(float4*)&As[arow * AS_STR + acol]        = ra0;
        *(float4*)&As[(arow + 32) * AS_STR + acol] = ra1;
        *(float4*)&Bs[brow * BS_STR + bcol]        = rb0;
        *(float4*)&Bs[brow * BS_STR + bcol + 4]    = rb1;
        __syncthreads();
        if (s < 15) {
            ra0 = *(const float4*)(Ap + (s + 1) * 16);
            ra1 = *(const float4*)(Ap + (s + 1) * 16 + 32 * 256);
            rb0 = *(const float4*)(Wp + (s + 1) * 16 * 256);
            rb1 = *(const float4*)(Wp + (s + 1) * 16 * 256 + 4);
        }
#pragma unroll
        for (int kq = 0; kq < 16; kq += 4) {
            // a-fragments: 8 float4 loads, transposed into scalar regs [kk][mi]
            float a_s[4][8];
#pragma unroll
            for (int i = 0; i < 4; i++) {
                float4 lo = *(const float4*)&As[(4 * ty + i) * AS_STR + kq];
                float4 hi = *(const float4*)&As[(32 + 4 * ty + i) * AS_STR + kq];
                a_s[0][i] = lo.x; a_s[1][i] = lo.y; a_s[2][i] = lo.z; a_s[3][i] = lo.w;
                a_s[0][i + 4] = hi.x; a_s[1][i + 4] = hi.y;
                a_s[2][i + 4] = hi.z; a_s[3][i + 4] = hi.w;
            }
            // b-fragments: 4 float4 loads [kk]
            float4 b4[4];
#pragma unroll
            for (int kk = 0; kk < 4; kk++)
                b4[kk] = *(const float4*)&Bs[(kq + kk) * BS_STR + 4 * tx];
#pragma unroll
            for (int kk = 0; kk < 4; kk++) {
#pragma unroll
                for (int mi = 0; mi < 8; mi++) {
                    float av = a_s[kk][mi];
                    acc[mi][0] = fmaf(av, b4[kk].x, acc[mi][0]);
                    acc[mi][1] = fmaf(av, b4[kk].y, acc[mi][1]);
                    acc[mi][2] = fmaf(av, b4[kk].z, acc[mi][2]);
                    acc[mi][3] = fmaf(av, b4[kk].w, acc[mi][3]);
                }
            }
        }
        __syncthreads();
    }
#pragma unroll
    for (int mi = 0; mi < 8; mi++) {
        int m = m0 + ((mi < 4) ? (4 * ty + mi) : (32 + 4 * ty + (mi - 4)));
        float4 o;
        o.x = ex2f(acc[mi][0] * TWO_LOG2E);
        o.y = ex2f(acc[mi][1] * TWO_LOG2E);
        o.z = ex2f(acc[mi][2] * TWO_LOG2E);
        o.w = ex2f(acc[mi][3] * TWO_LOG2E);
        *(float4*)&C[m * 256 + n0 + 4 * tx] = o;
    }
}

// ---------------------------------------------------------------------------
// Threefry-2x32, key = (0,1) [jax.random.key(1)], partitionable bits.
// ---------------------------------------------------------------------------
__device__ __forceinline__ uint32_t rotl32(uint32_t v, int r) {
    return __funnelshift_l(v, v, r);
}
__device__ __forceinline__ uint32_t threefry_bits(uint32_t idx) {
    const uint32_t K0 = 0u, K1 = 1u, K2 = 0x1BD11BDBu;
    uint32_t x0 = K0;
    uint32_t x1 = idx + K1;
#define TF_ROUND(r) { x0 += x1; x1 = rotl32(x1, (r)); x1 ^= x0; }
    TF_ROUND(13) TF_ROUND(15) TF_ROUND(26) TF_ROUND(6)
    x0 += K1; x1 += K2 + 1u;
    TF_ROUND(17) TF_ROUND(29) TF_ROUND(16) TF_ROUND(24)
    x0 += K2; x1 += K0 + 2u;
    TF_ROUND(13) TF_ROUND(15) TF_ROUND(26) TF_ROUND(6)
    x0 += K0; x1 += K1 + 3u;
    TF_ROUND(17) TF_ROUND(29) TF_ROUND(16) TF_ROUND(24)
    x0 += K1; x1 += K2 + 4u;
    TF_ROUND(13) TF_ROUND(15) TF_ROUND(26) TF_ROUND(6)
    x0 += K2; x1 += K0 + 5u;
#undef TF_ROUND
    return x0 ^ x1;
}

// Epilogue for one (b,i,j): writes ms/sample/entropy, counts sample into
// g_cnt (integer atomic -> deterministic), returns (entropy, lsm_term).
__device__ __forceinline__ float2 epi_one(int b, int i, int j, float logit,
                                          float* __restrict__ out) {
    float ms = (i == j) ? (logit - 1e8f) : logit;
    uint32_t f = ((uint32_t)b << 14) | ((uint32_t)i << 7) | (uint32_t)j;
    uint32_t bits = threefry_bits(f);
    float u = __uint_as_float((bits >> 9) | 0x3f800000u) - 1.0f;
    float p = 1.0f / (1.0f + expf(-ms));
    float c = log1pf(expf(-fabsf(ms)));          // shared softplus tail
    float sp_pos = fmaxf(ms, 0.0f) + c;          // softplus(ms)
    float sp_neg = fmaxf(-ms, 0.0f) + c;         // softplus(-ms)
    float ent = fmaf(p, sp_neg, (1.0f - p) * sp_pos);
    float s;
    if (u < p) { s = 1.0f; atomicAdd(&g_cnt[i * LL + j], 1); } else s = 0.0f;
    out[OFF_MS + f] = ms;
    out[OFF_S + f]  = s;
    out[OFF_E + f]  = ent;
    float lsm = sp_pos - ms * s;
    return make_float2(ent, lsm);
}

// ---------------------------------------------------------------------------
// Pairwise core. tanh(l+r) = 1 - 2/(1 + el*er); logit = -2*sum U*(r-0.5) + bias.
// grid (8, 4, 16): x = j-tile(16), y = i-tile(32), z = batch; 256 threads
// (ty = i 0..31, tx = j 0..7; each thread does j and j+8). Full D=256 smem.
// 512 blocks @ occ 4 (592 slots) -> strictly ONE wave, no quantization.
// ---------------------------------------------------------------------------
#define PW_STR 260

__global__ __launch_bounds__(256, 4)
void pairwise_kernel(const float* __restrict__ Uv,
                     const float* __restrict__ biasp,
                     float* __restrict__ out) {
    __shared__ __align__(16) float sl[32 * PW_STR];
    __shared__ __align__(16) float sr[16 * PW_STR];
    __shared__ __align__(16) float su[256];
    __shared__ float rshare[2][8];
    const int tid = threadIdx.x;
    const int tx = tid & 7, ty = tid >> 3;        // j, i within tile
    const int b = blockIdx.z;
    const int ibase = blockIdx.y * 32, jbase = blockIdx.x * 16;

    su[tid] = Uv[tid];
    // load 32 l-rows + 16 r-rows, each 256 floats (64 float4), coalesced
    for (int idx = tid; idx < 48 * 64; idx += 256) {
        int r = idx >> 6, c = (idx & 63) * 4;
        if (r < 32) {
            *(float4*)&sl[r * PW_STR + c] =
                *(const float4*)&g_el[(b * 128 + ibase + r) * 256 + c];
        } else {
            *(float4*)&sr[(r - 32) * PW_STR + c] =
                *(const float4*)&g_er[(b * 128 + jbase + (r - 32)) * 256 + c];
        }
    }
    __syncthreads();

    const float* pl  = sl + ty * PW_STR;
    const float* pr0 = sr + tx * PW_STR;
    const float* pr1 = sr + (tx + 8) * PW_STR;
    float a0 = 0.0f, a1 = 0.0f;
#pragma unroll 4
    for (int d = 0; d < 256; d += 4) {
        float4 L  = *(const float4*)(pl + d);
        float4 R0 = *(const float4*)(pr0 + d);
        float4 R1 = *(const float4*)(pr1 + d);
        float4 UD = *(const float4*)(su + d);
        a0 = fmaf(UD.x, rcpf(fmaf(L.x, R0.x, 1.0f)) - 0.5f, a0);
        a1 = fmaf(UD.x, rcpf(fmaf(L.x, R1.x, 1.0f)) - 0.5f, a1);
        a0 = fmaf(UD.y, rcpf(fmaf(L.y, R0.y, 1.0f)) - 0.5f, a0);
        a1 = fmaf(UD.y, rcpf(fmaf(L.y, R1.y, 1.0f)) - 0.5f, a1);
        a0 = fmaf(UD.z, rcpf(fmaf(L.z, R0.z, 1.0f)) - 0.5f, a0);
        a1 = fmaf(UD.z, rcpf(fmaf(L.z, R1.z, 1.0f)) - 0.5f, a1);
        a0 = fmaf(UD.w, rcpf(fmaf(L.w, R0.w, 1.0f)) - 0.5f, a0);
        a1 = fmaf(UD.w, rcpf(fmaf(L.w, R1.w, 1.0f)) - 0.5f, a1);
    }

    const float bias = __ldg(biasp);
    float2 e0 = epi_one(b, ibase + ty, jbase + tx,     fmaf(-2.0f, a0, bias), out);
    float2 e1 = epi_one(b, ibase + ty, jbase + tx + 8, fmaf(-2.0f, a1, bias), out);

    // block reduce (shfl tree + 8-warp combine), deterministic
    float ent = e0.x + e1.x, lsm = e0.y + e1.y;
#pragma unroll
    for (int o = 16; o > 0; o >>= 1) {
        ent += __shfl_xor_sync(0xffffffffu, ent, o);
        lsm += __shfl_xor_sync(0xffffffffu, lsm, o);
    }
    const int wid = tid >> 5;
    if ((tid & 31) == 0) { rshare[0][wid] = ent; rshare[1][wid] = lsm; }
    __syncthreads();
    if (tid == 0) {
        float se = 0.0f, sm = 0.0f;
#pragma unroll
        for (int w = 0; w < 8; w++) { se += rshare[0][w]; sm += rshare[1][w]; }
        const int bid = (b * 4 + blockIdx.y) * 8 + blockIdx.x; // 0..511
        g_ent_part[bid] = se;
        g_lsm_part[bid] = sm;
    }
}

// ---------------------------------------------------------------------------
// Tail: blocks 0-63 convert+reset graph_batch counts; block 64 finishes
// entropy_regularization (16 per-batch sums of 32 partials, fixed order)
// and the log_softmax scalar (one warp reduces 512 partials).
// ---------------------------------------------------------------------------
__global__ void tail_kernel(float* __restrict__ out) {
    const int bidx = blockIdx.x;
    if (bidx < 64) {
        int idx = bidx * 256 + threadIdx.x;   // 0..16383
        out[OFF_GB + idx] = (float)g_cnt[idx] * 0.0625f;
        g_cnt[idx] = 0;                        // reset for next graph replay
    } else {
        int t = threadIdx.x;
        if (t < 16) {
            float s = 0.0f;
#pragma unroll
            for (int k = 0; k < 32; k++) s += g_ent_part[t * 32 + k];
            out[OFF_ER + t] = s * (1.0f / 16384.0f);
        }
        if (t >= 32 && t < 64) {
            int lane = t - 32;
            float s = 0.0f;
#pragma unroll
            for (int k = 0; k < 16; k++) s += g_lsm_part[lane * 16 + k];
#pragma unroll
            for (int o = 16; o > 0; o >>= 1)
                s += __shfl_xor_sync(0xffffffffu, s, o);
            if (lane == 0) out[OFF_LSM] = s * (1.0f / (float)NEL);
        }
    }
}

// ---------------------------------------------------------------------------
extern "C" void kernel_launch(void* const* d_in, const int* in_sizes, int n_in,
                              void* d_out, int out_size) {
    (void)in_sizes; (void)n_in; (void)out_size;
    const float* enc  = (const float*)d_in[0]; // (16,128,256)
    const float* W_l  = (const float*)d_in[1]; // (256,256)
    const float* W_r  = (const float*)d_in[2]; // (256,256)
    const float* U    = (const float*)d_in[3]; // (256,)
    const float* bias = (const float*)d_in[4]; // (1,)
    float* out = (float*)d_out;

    gemm_exp_kernel<<<dim3(4, 32, 2), 128>>>(enc, W_l, W_r);
    pairwise_kernel<<<dim3(8, 4, 16), 256>>>(U, bias, out);
    tail_kernel<<<65, 256>>>(out);
}